// round 14
// baseline (speedup 1.0000x reference)
#include <cuda_runtime.h>
#include <cuda_fp16.h>
#include <math.h>
#include <stdint.h>

// ---------------------------------------------------------------------------
// GodAreaModel via mma.sync fp16, single-term (C = A*Bh).
// R13: dual-stream prep overlap (W-split || encode), LOG_SPLIT=16.
// Tick GEMM is at ~86% of its smem-crossbar ceiling; left unchanged.
// ---------------------------------------------------------------------------

#define A_NUM   4
#define AREA_N  2048
#define NTOT    8192
#define D_INPUT 1024
#define NCLS    1024
#define BATCH   512
#define NTICKS  4
#define THRESH  0.05f
#define LOGITS_ELEMS (BATCH * NCLS)
#define HIST_STEP    (A_NUM * BATCH * AREA_N)

// Block tile
#define BM 128
#define BN 128
#define BK 64
#define A_TILE_BYTES (BM * BK * 2)          // 16384
#define B_TILE_BYTES (BN * BK * 2)          // 16384
#define ST_BYTES (A_TILE_BYTES + B_TILE_BYTES)  // 32768
#define NST 3
#define SMEM_DYN (NST * ST_BYTES)           // 98304 -> 2 CTAs/SM

#define LOG_SPLIT 16
#define LOG_KTILES (NTOT / BK / LOG_SPLIT)  // 8

// ------------------------- device scratch -------------------------
__device__ __align__(256) __half g_Whi[(size_t)NTOT * NTOT];
__device__ __align__(256) __half g_Rhi[(size_t)NTOT * D_INPUT];
__device__ __align__(256) __half g_Ohi[(size_t)NCLS * NTOT];
__device__ __align__(256) __half g_xf [(size_t)BATCH * D_INPUT];
__device__ __align__(256) __half g_Zf0[(size_t)BATCH * NTOT];
__device__ __align__(256) __half g_Zf1[(size_t)BATCH * NTOT];
__device__ __align__(256) float g_part[(size_t)LOG_SPLIT * LOGITS_ELEMS];
__device__ __align__(256) float g_tsA[256];
__device__ __align__(256) float g_tsB[256];

// ------------------------- helpers -------------------------
__device__ __forceinline__ uint32_t smem_u32(const void* p) {
    return (uint32_t)__cvta_generic_to_shared(p);
}
__device__ __forceinline__ uint32_t pack2h(__half a, __half b) {
    __half2 v; v.x = a; v.y = b;
    return *reinterpret_cast<uint32_t*>(&v);
}
__device__ __forceinline__ void cp16(uint32_t saddr, const void* g) {
    asm volatile("cp.async.cg.shared.global [%0], [%1], 16;" :: "r"(saddr), "l"(g));
}
template<int N>
__device__ __forceinline__ void cp_wait() {
    asm volatile("cp.async.wait_group %0;" :: "n"(N) : "memory");
}
__device__ __forceinline__ uint32_t swz(uint32_t row, uint32_t chunk) {
    return row * 128u + ((chunk ^ (row & 7u)) << 4);
}
__device__ __forceinline__ void ldsm4(uint32_t addr, uint32_t* r) {
    asm volatile("ldmatrix.sync.aligned.m8n8.x4.shared.b16 {%0,%1,%2,%3}, [%4];"
                 : "=r"(r[0]), "=r"(r[1]), "=r"(r[2]), "=r"(r[3]) : "r"(addr));
}
__device__ __forceinline__ void mma16816(float* c, const uint32_t* a, const uint32_t* b) {
    asm volatile(
        "mma.sync.aligned.m16n8k16.row.col.f32.f16.f16.f32 "
        "{%0,%1,%2,%3}, {%4,%5,%6,%7}, {%8,%9}, {%0,%1,%2,%3};"
        : "+f"(c[0]), "+f"(c[1]), "+f"(c[2]), "+f"(c[3])
        : "r"(a[0]), "r"(a[1]), "r"(a[2]), "r"(a[3]), "r"(b[0]), "r"(b[1]));
}

// ------------------------- prep kernels -------------------------
__global__ void prep_wsplit(const float4* __restrict__ W, const float4* __restrict__ mask) {
    const size_t total = (size_t)NTOT * NTOT / 4;
    const size_t stride = (size_t)gridDim.x * blockDim.x;
    for (size_t q = (size_t)blockIdx.x * blockDim.x + threadIdx.x; q < total; q += stride) {
        float4 w  = W[q];
        float4 mk = mask[q];
        float v0 = w.x * fminf(fmaxf(mk.x, 0.f), 1.f);
        float v1 = w.y * fminf(fmaxf(mk.y, 0.f), 1.f);
        float v2 = w.z * fminf(fmaxf(mk.z, 0.f), 1.f);
        float v3 = w.w * fminf(fmaxf(mk.w, 0.f), 1.f);
        size_t s = q * 4;
        int m = (int)(s & 2047);
        size_t r = s >> 11;
        int n = (int)(r & 2047); r >>= 11;
        int i = (int)(r & 3);
        int o = (int)(r >> 2);
        size_t dst = ((size_t)((o << 11) | n)) * NTOT + ((i << 11) | m);
        uint2 out;
        out.x = pack2h(__float2half_rn(v0), __float2half_rn(v1));
        out.y = pack2h(__float2half_rn(v2), __float2half_rn(v3));
        *(uint2*)(g_Whi + dst) = out;
    }
}
__global__ void prep_rhalf(const float4* __restrict__ Rw) {
    const size_t total = (size_t)NTOT * D_INPUT / 4;
    const size_t stride = (size_t)gridDim.x * blockDim.x;
    for (size_t q = (size_t)blockIdx.x * blockDim.x + threadIdx.x; q < total; q += stride) {
        float4 w = Rw[q];
        uint2 out;
        out.x = pack2h(__float2half_rn(w.x), __float2half_rn(w.y));
        out.y = pack2h(__float2half_rn(w.z), __float2half_rn(w.w));
        *(uint2*)(g_Rhi + q * 4) = out;
    }
}
__global__ void prep_ohalf(const float* __restrict__ Ow, const int* __restrict__ aidx) {
    size_t s = ((size_t)blockIdx.x * blockDim.x + threadIdx.x) * 2;
    int k = (int)(s & 8191);
    int c = (int)(s >> 13);
    float w0 = Ow[(size_t)c * NTOT + aidx[k]];
    float w1 = Ow[(size_t)c * NTOT + aidx[k + 1]];
    *(uint32_t*)(g_Ohi + s) = pack2h(__float2half_rn(w0), __float2half_rn(w1));
}
__global__ void prep_xf(const float* __restrict__ x) {
    size_t s = ((size_t)blockIdx.x * blockDim.x + threadIdx.x) * 2;
    float2 w = *(const float2*)(x + s);
    *(uint32_t*)(g_xf + s) = pack2h(__float2half_rn(w.x), __float2half_rn(w.y));
}
__global__ void logits_reduce(const float* __restrict__ Ob, float* __restrict__ out) {
    int i = (blockIdx.x * 256 + threadIdx.x) * 4;
    float4 a = *(const float4*)(g_part + i);
    #pragma unroll
    for (int s = 1; s < LOG_SPLIT; s++) {
        float4 b = *(const float4*)(g_part + (size_t)s * LOGITS_ELEMS + i);
        a.x += b.x; a.y += b.y; a.z += b.z; a.w += b.w;
    }
    int n = i & (NCLS - 1);
    float4 ob = *(const float4*)(Ob + n);
    a.x += ob.x; a.y += ob.y; a.z += ob.z; a.w += ob.w;
    *(float4*)(out + i) = a;
}

// ------------------------- stage loader (128 threads) -------------------------
__device__ __forceinline__ void load_tile128(uint32_t sb, const __half* g, int ld, int tid) {
    #pragma unroll
    for (int r = 0; r < 8; r++) {
        int id = tid + r * 128;
        uint32_t row = (uint32_t)id >> 3, c = (uint32_t)id & 7;
        cp16(sb + swz(row, c), g + (size_t)row * ld + c * 8);
    }
}
__device__ __forceinline__ void load_stage(
    uint32_t sb, const __half* Af, const __half* Bh,
    int m0, int n0, int k0, int ld, int tid)
{
    load_tile128(sb,                Af + (size_t)m0 * ld + k0, ld, tid);
    load_tile128(sb + A_TILE_BYTES, Bh + (size_t)n0 * ld + k0, ld, tid);
    asm volatile("cp.async.commit_group;" ::: "memory");
}

// ------------------------- main GEMM -------------------------
// grid (N/BN, M/BM, zsplit). 4 warps: 2(m) x 2(n), warp tile 64x64.
__global__ __launch_bounds__(128, 2)
void god_gemm(const __half* __restrict__ Af, const __half* __restrict__ Bh,
              int ldk, int ktiles_in,
              int use_gate,
              const float* __restrict__ tsum_in,
              const float* __restrict__ bias,
              const float* __restrict__ bb4,
              float* __restrict__ hist,
              float* __restrict__ logits, int logitsN, size_t zstride,
              __half* __restrict__ Zfo,
              float* __restrict__ tsum_out,
              int do_tanh)
{
    extern __shared__ char dsm[];
    __shared__ float s_gate[A_NUM];
    __shared__ float s_wsum[4];

    const int tid  = threadIdx.x;
    const int wid  = tid >> 5, lane = tid & 31;
    const int wm   = wid >> 1;
    const int wn   = wid & 1;
    const int m0   = blockIdx.y * BM;
    const int n0   = blockIdx.x * BN;
    const int k0tile = blockIdx.z * ktiles_in;
    const uint32_t sbase = smem_u32(dsm);
    if (logits) logits += (size_t)blockIdx.z * zstride;

    // gates from previous kernel's tilesums (deterministic, fixed order)
    if (tid < A_NUM) {
        float g = 1.0f;
        if (use_gate) {
            float s = 0.0f;
            #pragma unroll
            for (int y = 0; y < 4; y++)
                for (int xx = 0; xx < 16; xx++)
                    s += __ldg(tsum_in + y * 64 + tid * 16 + xx);
            g = (s * (1.0f / (float)(BATCH * AREA_N)) > THRESH) ? 1.0f : 0.0f;
        }
        s_gate[tid] = g;
    }
    __syncthreads();

    int aa[A_NUM];
    int nact;
    if (use_gate) {
        int c = 0;
        #pragma unroll
        for (int a = 0; a < A_NUM; a++)
            if (s_gate[a] != 0.0f) aa[c++] = a;
        nact = c * 32;
    } else {
        nact = ktiles_in;
        aa[0] = 0;
    }
    #define KT(i) (use_gate ? (aa[(i) >> 5] * 32 + ((i) & 31)) : (k0tile + (i)))

    float acc[4][8][4];
    #pragma unroll
    for (int a = 0; a < 4; a++)
        #pragma unroll
        for (int b = 0; b < 8; b++)
            #pragma unroll
            for (int c = 0; c < 4; c++) acc[a][b][c] = 0.0f;

    const uint32_t a_row = (lane & 7) + ((lane >> 3) & 1) * 8;
    const uint32_t a_ch  = (lane >> 4);
    const uint32_t b_row = (lane & 7) + (lane >> 4) * 8;
    const uint32_t b_ch  = (lane >> 3) & 1;
    const uint32_t arow_s = wm * 64 + a_row;
    const uint32_t brow_s = wn * 64 + b_row;

    #pragma unroll
    for (int s = 0; s < NST - 1; s++)
        if (s < nact)
            load_stage(sbase + (uint32_t)s * ST_BYTES, Af, Bh,
                       m0, n0, KT(s) * BK, ldk, tid);

    uint32_t ah[2][4][4], bh[2][4][4];

    int sl = 0;
    #pragma unroll 1
    for (int i = 0; i < nact; i++) {
        if (nact - i - 1 >= NST - 2) cp_wait<NST - 2>();
        else                         cp_wait<0>();
        __syncthreads();

        if (i + NST - 1 < nact) {
            int s2 = sl + NST - 1; if (s2 >= NST) s2 -= NST;
            load_stage(sbase + (uint32_t)s2 * ST_BYTES, Af, Bh,
                       m0, n0, KT(i + NST - 1) * BK, ldk, tid);
        }

        const uint32_t sA = sbase + (uint32_t)sl * ST_BYTES;
        const uint32_t sB = sA + A_TILE_BYTES;

        #pragma unroll
        for (int ng = 0; ng < 4; ng++)
            ldsm4(sB + swz(brow_s + ng * 16, b_ch), bh[0][ng]);
        #pragma unroll
        for (int mt = 0; mt < 4; mt++)
            ldsm4(sA + swz(arow_s + mt * 16, a_ch), ah[0][mt]);

        #pragma unroll
        for (int ks = 0; ks < 4; ks++) {
            const int cur = ks & 1, nxt = cur ^ 1;
            if (ks < 3) {
                #pragma unroll
                for (int ng = 0; ng < 4; ng++)
                    ldsm4(sB + swz(brow_s + ng * 16, (ks + 1) * 2 + b_ch), bh[nxt][ng]);
                #pragma unroll
                for (int mt = 0; mt < 4; mt++)
                    ldsm4(sA + swz(arow_s + mt * 16, (ks + 1) * 2 + a_ch), ah[nxt][mt]);
            }
            #pragma unroll
            for (int mt = 0; mt < 4; mt++)
                #pragma unroll
                for (int nt = 0; nt < 8; nt++)
                    mma16816(acc[mt][nt], ah[cur][mt], bh[cur][nt >> 1] + (nt & 1) * 2);
        }
        sl++; if (sl == NST) sl = 0;
    }

    // ---- epilogue: (gated) bias + tanh + hist/logits/Z + |Z| partial ----
    float asum = 0.0f;
    const int lrow = lane >> 2;
    const int lcol = (lane & 3) * 2;
    #pragma unroll
    for (int mt = 0; mt < 4; mt++) {
        #pragma unroll
        for (int half = 0; half < 2; half++) {
            const int m = m0 + wm * 64 + mt * 16 + lrow + half * 8;
            #pragma unroll
            for (int nt = 0; nt < 8; nt++) {
                const int n = n0 + wn * 64 + nt * 8 + lcol;
                float b0 = 0.0f, b1 = 0.0f;
                if (bb4) {
                    int o = n >> 11, nn = n & 2047;
                    #pragma unroll
                    for (int ia = 0; ia < A_NUM; ia++) {
                        const float* row = bb4 + (size_t)(o * A_NUM + ia) * AREA_N + nn;
                        b0 += s_gate[ia] * __ldg(row);
                        b1 += s_gate[ia] * __ldg(row + 1);
                    }
                } else if (bias) {
                    b0 = __ldg(bias + n);
                    b1 = __ldg(bias + n + 1);
                }
                float v0 = acc[mt][nt][half * 2 + 0] + b0;
                float v1 = acc[mt][nt][half * 2 + 1] + b1;
                if (do_tanh) { v0 = tanhf(v0); v1 = tanhf(v1); }
                asum += fabsf(v0) + fabsf(v1);
                if (hist) {
                    int a = n >> 11, nn = n & 2047;
                    *(float2*)(hist + ((size_t)a * BATCH + m) * AREA_N + nn) =
                        make_float2(v0, v1);
                }
                if (logits)
                    *(float2*)(logits + (size_t)m * logitsN + n) = make_float2(v0, v1);
                if (Zfo)
                    *(uint32_t*)(Zfo + (size_t)m * NTOT + n) =
                        pack2h(__float2half_rn(v0), __float2half_rn(v1));
            }
        }
    }

    if (tsum_out) {
        #pragma unroll
        for (int o = 16; o; o >>= 1) asum += __shfl_xor_sync(0xffffffffu, asum, o);
        if (lane == 0) s_wsum[wid] = asum;
        __syncthreads();
        if (tid == 0)
            tsum_out[blockIdx.y * 64 + blockIdx.x] =
                (s_wsum[0] + s_wsum[1]) + (s_wsum[2] + s_wsum[3]);
    }
}

// ------------------------- launch -------------------------
extern "C" void kernel_launch(void* const* d_in, const int* in_sizes, int n_in,
                              void* d_out, int out_size) {
    const float* x    = (const float*)d_in[0];
    const float* Rw   = (const float*)d_in[1];
    const float* rb   = (const float*)d_in[2];
    const float* Wb   = (const float*)d_in[3];
    const float* bb   = (const float*)d_in[4];
    const float* mask = (const float*)d_in[5];
    const float* Ow   = (const float*)d_in[6];
    const float* Ob   = (const float*)d_in[7];
    const int*   aidx = (const int*)d_in[8];

    float* out  = (float*)d_out;
    float* hist = out + LOGITS_ELEMS;

    __half *whi, *rhi, *ohi, *xf, *zf[2];
    float *ts[2], *part;
    cudaGetSymbolAddress((void**)&whi, g_Whi);
    cudaGetSymbolAddress((void**)&rhi, g_Rhi);
    cudaGetSymbolAddress((void**)&ohi, g_Ohi);
    cudaGetSymbolAddress((void**)&xf,  g_xf);
    cudaGetSymbolAddress((void**)&zf[0], g_Zf0);
    cudaGetSymbolAddress((void**)&zf[1], g_Zf1);
    cudaGetSymbolAddress((void**)&ts[0], g_tsA);
    cudaGetSymbolAddress((void**)&ts[1], g_tsB);
    cudaGetSymbolAddress((void**)&part,  g_part);

    cudaFuncSetAttribute(god_gemm, cudaFuncAttributeMaxDynamicSharedMemorySize, SMEM_DYN);

    // Side stream for independent prep (W-split feeds tick 1; O-gather feeds
    // logits). Created fresh per call (host-side resource, not device memory);
    // fork/join via events so both branches are inside the same capture.
    cudaStream_t s2;
    cudaStreamCreateWithFlags(&s2, cudaStreamNonBlocking);
    cudaEvent_t eFork, eJoin;
    cudaEventCreateWithFlags(&eFork, cudaEventDisableTiming);
    cudaEventCreateWithFlags(&eJoin, cudaEventDisableTiming);

    cudaEventRecord(eFork, 0);
    cudaStreamWaitEvent(s2, eFork, 0);

    // side branch: heavy streaming preps (no dependency on encode)
    prep_wsplit<<<4096, 256, 0, s2>>>((const float4*)Wb, (const float4*)mask);
    prep_ohalf<<<16384, 256, 0, s2>>>(Ow, aidx);
    cudaEventRecord(eJoin, s2);

    // main branch: encode-path preps + encode GEMM
    prep_xf<<<1024, 256>>>(x);
    prep_rhalf<<<2048, 256>>>((const float4*)Rw);
    god_gemm<<<dim3(64, 4), 128, SMEM_DYN>>>(
        xf, rhi, D_INPUT, D_INPUT / BK,
        0, nullptr, rb, nullptr,
        hist, nullptr, 0, 0,
        zf[0], ts[0], 1);

    // join: ticks need g_Whi
    cudaStreamWaitEvent(0, eJoin, 0);

    // ticks (K=8192, area-gated; gates+bias fused; tsum ping-pong)
    int p = 0;
    for (int t = 0; t < NTICKS; t++) {
        god_gemm<<<dim3(64, 4), 128, SMEM_DYN>>>(
            zf[p], whi, NTOT, 0,
            1, ts[t & 1], nullptr, bb,
            hist + (size_t)(t + 1) * HIST_STEP, nullptr, 0, 0,
            zf[1 - p], ts[(t & 1) ^ 1], 1);
        p ^= 1;
    }

    // logits: one 3D launch, 16-way split-K, then reduce (+Ob)
    god_gemm<<<dim3(8, 4, LOG_SPLIT), 128, SMEM_DYN>>>(
        zf[p], ohi, NTOT, LOG_KTILES,
        0, nullptr, nullptr, nullptr,
        nullptr, part, NCLS, (size_t)LOGITS_ELEMS,
        nullptr, nullptr, 0);
    logits_reduce<<<LOGITS_ELEMS / 1024, 256>>>(Ob, out);
}

// round 15
// speedup vs baseline: 1.4762x; 1.4762x over previous
#include <cuda_runtime.h>
#include <cuda_fp16.h>
#include <math.h>
#include <stdint.h>

// ---------------------------------------------------------------------------
// GodAreaModel via mma.sync fp16, single-term (C = A*Bh).
// R14: single stream (R13 fork reverted); prep_wsplit widened to 8 floats/iter
// (MLP 4) for ~2x streaming throughput; LOG_SPLIT=16 kept.
// ---------------------------------------------------------------------------

#define A_NUM   4
#define AREA_N  2048
#define NTOT    8192
#define D_INPUT 1024
#define NCLS    1024
#define BATCH   512
#define NTICKS  4
#define THRESH  0.05f
#define LOGITS_ELEMS (BATCH * NCLS)
#define HIST_STEP    (A_NUM * BATCH * AREA_N)

// Block tile
#define BM 128
#define BN 128
#define BK 64
#define A_TILE_BYTES (BM * BK * 2)          // 16384
#define B_TILE_BYTES (BN * BK * 2)          // 16384
#define ST_BYTES (A_TILE_BYTES + B_TILE_BYTES)  // 32768
#define NST 3
#define SMEM_DYN (NST * ST_BYTES)           // 98304 -> 2 CTAs/SM

#define LOG_SPLIT 16
#define LOG_KTILES (NTOT / BK / LOG_SPLIT)  // 8

// ------------------------- device scratch -------------------------
__device__ __align__(256) __half g_Whi[(size_t)NTOT * NTOT];
__device__ __align__(256) __half g_Rhi[(size_t)NTOT * D_INPUT];
__device__ __align__(256) __half g_Ohi[(size_t)NCLS * NTOT];
__device__ __align__(256) __half g_xf [(size_t)BATCH * D_INPUT];
__device__ __align__(256) __half g_Zf0[(size_t)BATCH * NTOT];
__device__ __align__(256) __half g_Zf1[(size_t)BATCH * NTOT];
__device__ __align__(256) float g_part[(size_t)LOG_SPLIT * LOGITS_ELEMS];
__device__ __align__(256) float g_tsA[256];
__device__ __align__(256) float g_tsB[256];

// ------------------------- helpers -------------------------
__device__ __forceinline__ uint32_t smem_u32(const void* p) {
    return (uint32_t)__cvta_generic_to_shared(p);
}
__device__ __forceinline__ uint32_t pack2h(__half a, __half b) {
    __half2 v; v.x = a; v.y = b;
    return *reinterpret_cast<uint32_t*>(&v);
}
__device__ __forceinline__ void cp16(uint32_t saddr, const void* g) {
    asm volatile("cp.async.cg.shared.global [%0], [%1], 16;" :: "r"(saddr), "l"(g));
}
template<int N>
__device__ __forceinline__ void cp_wait() {
    asm volatile("cp.async.wait_group %0;" :: "n"(N) : "memory");
}
__device__ __forceinline__ uint32_t swz(uint32_t row, uint32_t chunk) {
    return row * 128u + ((chunk ^ (row & 7u)) << 4);
}
__device__ __forceinline__ void ldsm4(uint32_t addr, uint32_t* r) {
    asm volatile("ldmatrix.sync.aligned.m8n8.x4.shared.b16 {%0,%1,%2,%3}, [%4];"
                 : "=r"(r[0]), "=r"(r[1]), "=r"(r[2]), "=r"(r[3]) : "r"(addr));
}
__device__ __forceinline__ void mma16816(float* c, const uint32_t* a, const uint32_t* b) {
    asm volatile(
        "mma.sync.aligned.m16n8k16.row.col.f32.f16.f16.f32 "
        "{%0,%1,%2,%3}, {%4,%5,%6,%7}, {%8,%9}, {%0,%1,%2,%3};"
        : "+f"(c[0]), "+f"(c[1]), "+f"(c[2]), "+f"(c[3])
        : "r"(a[0]), "r"(a[1]), "r"(a[2]), "r"(a[3]), "r"(b[0]), "r"(b[1]));
}
__device__ __forceinline__ uint2 clamp_pack8_lo(float4 w, float4 mk) {
    float v0 = w.x * fminf(fmaxf(mk.x, 0.f), 1.f);
    float v1 = w.y * fminf(fmaxf(mk.y, 0.f), 1.f);
    float v2 = w.z * fminf(fmaxf(mk.z, 0.f), 1.f);
    float v3 = w.w * fminf(fmaxf(mk.w, 0.f), 1.f);
    uint2 r;
    r.x = pack2h(__float2half_rn(v0), __float2half_rn(v1));
    r.y = pack2h(__float2half_rn(v2), __float2half_rn(v3));
    return r;
}

// ------------------------- prep kernels -------------------------
// 8 floats per iteration: 4 independent float4 loads in flight (MLP~4),
// one coalesced uint4 store. Block-permuted destination, contiguous in m.
__global__ void prep_wsplit(const float4* __restrict__ W, const float4* __restrict__ mask) {
    const size_t total = (size_t)NTOT * NTOT / 8;
    const size_t stride = (size_t)gridDim.x * blockDim.x;
    for (size_t q = (size_t)blockIdx.x * blockDim.x + threadIdx.x; q < total; q += stride) {
        float4 w0  = W[q * 2];
        float4 w1  = W[q * 2 + 1];
        float4 mk0 = mask[q * 2];
        float4 mk1 = mask[q * 2 + 1];
        size_t s = q * 8;
        int m = (int)(s & 2047);
        size_t r = s >> 11;
        int n = (int)(r & 2047); r >>= 11;
        int i = (int)(r & 3);
        int o = (int)(r >> 2);
        size_t dst = ((size_t)((o << 11) | n)) * NTOT + ((i << 11) | m);
        uint2 lo = clamp_pack8_lo(w0, mk0);
        uint2 hi = clamp_pack8_lo(w1, mk1);
        uint4 out4;
        out4.x = lo.x; out4.y = lo.y; out4.z = hi.x; out4.w = hi.y;
        *(uint4*)(g_Whi + dst) = out4;
    }
}
__global__ void prep_rhalf(const float4* __restrict__ Rw) {
    const size_t total = (size_t)NTOT * D_INPUT / 8;
    const size_t stride = (size_t)gridDim.x * blockDim.x;
    for (size_t q = (size_t)blockIdx.x * blockDim.x + threadIdx.x; q < total; q += stride) {
        float4 w0 = Rw[q * 2];
        float4 w1 = Rw[q * 2 + 1];
        uint4 out4;
        out4.x = pack2h(__float2half_rn(w0.x), __float2half_rn(w0.y));
        out4.y = pack2h(__float2half_rn(w0.z), __float2half_rn(w0.w));
        out4.z = pack2h(__float2half_rn(w1.x), __float2half_rn(w1.y));
        out4.w = pack2h(__float2half_rn(w1.z), __float2half_rn(w1.w));
        *(uint4*)(g_Rhi + q * 8) = out4;
    }
}
__global__ void prep_ohalf(const float* __restrict__ Ow, const int* __restrict__ aidx) {
    size_t s = ((size_t)blockIdx.x * blockDim.x + threadIdx.x) * 4;
    int k = (int)(s & 8191);
    int c = (int)(s >> 13);
    const float* row = Ow + (size_t)c * NTOT;
    const int* ai = aidx + k;
    float w0 = row[ai[0]];
    float w1 = row[ai[1]];
    float w2 = row[ai[2]];
    float w3 = row[ai[3]];
    uint2 out;
    out.x = pack2h(__float2half_rn(w0), __float2half_rn(w1));
    out.y = pack2h(__float2half_rn(w2), __float2half_rn(w3));
    *(uint2*)(g_Ohi + s) = out;
}
__global__ void prep_xf(const float* __restrict__ x) {
    size_t s = ((size_t)blockIdx.x * blockDim.x + threadIdx.x) * 2;
    float2 w = *(const float2*)(x + s);
    *(uint32_t*)(g_xf + s) = pack2h(__float2half_rn(w.x), __float2half_rn(w.y));
}
__global__ void logits_reduce(const float* __restrict__ Ob, float* __restrict__ out) {
    int i = (blockIdx.x * 256 + threadIdx.x) * 4;
    float4 a = *(const float4*)(g_part + i);
    #pragma unroll
    for (int s = 1; s < LOG_SPLIT; s++) {
        float4 b = *(const float4*)(g_part + (size_t)s * LOGITS_ELEMS + i);
        a.x += b.x; a.y += b.y; a.z += b.z; a.w += b.w;
    }
    int n = i & (NCLS - 1);
    float4 ob = *(const float4*)(Ob + n);
    a.x += ob.x; a.y += ob.y; a.z += ob.z; a.w += ob.w;
    *(float4*)(out + i) = a;
}

// ------------------------- stage loader (128 threads) -------------------------
__device__ __forceinline__ void load_tile128(uint32_t sb, const __half* g, int ld, int tid) {
    #pragma unroll
    for (int r = 0; r < 8; r++) {
        int id = tid + r * 128;
        uint32_t row = (uint32_t)id >> 3, c = (uint32_t)id & 7;
        cp16(sb + swz(row, c), g + (size_t)row * ld + c * 8);
    }
}
__device__ __forceinline__ void load_stage(
    uint32_t sb, const __half* Af, const __half* Bh,
    int m0, int n0, int k0, int ld, int tid)
{
    load_tile128(sb,                Af + (size_t)m0 * ld + k0, ld, tid);
    load_tile128(sb + A_TILE_BYTES, Bh + (size_t)n0 * ld + k0, ld, tid);
    asm volatile("cp.async.commit_group;" ::: "memory");
}

// ------------------------- main GEMM -------------------------
// grid (N/BN, M/BM, zsplit). 4 warps: 2(m) x 2(n), warp tile 64x64.
__global__ __launch_bounds__(128, 2)
void god_gemm(const __half* __restrict__ Af, const __half* __restrict__ Bh,
              int ldk, int ktiles_in,
              int use_gate,
              const float* __restrict__ tsum_in,
              const float* __restrict__ bias,
              const float* __restrict__ bb4,
              float* __restrict__ hist,
              float* __restrict__ logits, int logitsN, size_t zstride,
              __half* __restrict__ Zfo,
              float* __restrict__ tsum_out,
              int do_tanh)
{
    extern __shared__ char dsm[];
    __shared__ float s_gate[A_NUM];
    __shared__ float s_wsum[4];

    const int tid  = threadIdx.x;
    const int wid  = tid >> 5, lane = tid & 31;
    const int wm   = wid >> 1;
    const int wn   = wid & 1;
    const int m0   = blockIdx.y * BM;
    const int n0   = blockIdx.x * BN;
    const int k0tile = blockIdx.z * ktiles_in;
    const uint32_t sbase = smem_u32(dsm);
    if (logits) logits += (size_t)blockIdx.z * zstride;

    // gates from previous kernel's tilesums (deterministic, fixed order)
    if (tid < A_NUM) {
        float g = 1.0f;
        if (use_gate) {
            float s = 0.0f;
            #pragma unroll
            for (int y = 0; y < 4; y++)
                for (int xx = 0; xx < 16; xx++)
                    s += __ldg(tsum_in + y * 64 + tid * 16 + xx);
            g = (s * (1.0f / (float)(BATCH * AREA_N)) > THRESH) ? 1.0f : 0.0f;
        }
        s_gate[tid] = g;
    }
    __syncthreads();

    int aa[A_NUM];
    int nact;
    if (use_gate) {
        int c = 0;
        #pragma unroll
        for (int a = 0; a < A_NUM; a++)
            if (s_gate[a] != 0.0f) aa[c++] = a;
        nact = c * 32;
    } else {
        nact = ktiles_in;
        aa[0] = 0;
    }
    #define KT(i) (use_gate ? (aa[(i) >> 5] * 32 + ((i) & 31)) : (k0tile + (i)))

    float acc[4][8][4];
    #pragma unroll
    for (int a = 0; a < 4; a++)
        #pragma unroll
        for (int b = 0; b < 8; b++)
            #pragma unroll
            for (int c = 0; c < 4; c++) acc[a][b][c] = 0.0f;

    const uint32_t a_row = (lane & 7) + ((lane >> 3) & 1) * 8;
    const uint32_t a_ch  = (lane >> 4);
    const uint32_t b_row = (lane & 7) + (lane >> 4) * 8;
    const uint32_t b_ch  = (lane >> 3) & 1;
    const uint32_t arow_s = wm * 64 + a_row;
    const uint32_t brow_s = wn * 64 + b_row;

    #pragma unroll
    for (int s = 0; s < NST - 1; s++)
        if (s < nact)
            load_stage(sbase + (uint32_t)s * ST_BYTES, Af, Bh,
                       m0, n0, KT(s) * BK, ldk, tid);

    uint32_t ah[2][4][4], bh[2][4][4];

    int sl = 0;
    #pragma unroll 1
    for (int i = 0; i < nact; i++) {
        if (nact - i - 1 >= NST - 2) cp_wait<NST - 2>();
        else                         cp_wait<0>();
        __syncthreads();

        if (i + NST - 1 < nact) {
            int s2 = sl + NST - 1; if (s2 >= NST) s2 -= NST;
            load_stage(sbase + (uint32_t)s2 * ST_BYTES, Af, Bh,
                       m0, n0, KT(i + NST - 1) * BK, ldk, tid);
        }

        const uint32_t sA = sbase + (uint32_t)sl * ST_BYTES;
        const uint32_t sB = sA + A_TILE_BYTES;

        #pragma unroll
        for (int ng = 0; ng < 4; ng++)
            ldsm4(sB + swz(brow_s + ng * 16, b_ch), bh[0][ng]);
        #pragma unroll
        for (int mt = 0; mt < 4; mt++)
            ldsm4(sA + swz(arow_s + mt * 16, a_ch), ah[0][mt]);

        #pragma unroll
        for (int ks = 0; ks < 4; ks++) {
            const int cur = ks & 1, nxt = cur ^ 1;
            if (ks < 3) {
                #pragma unroll
                for (int ng = 0; ng < 4; ng++)
                    ldsm4(sB + swz(brow_s + ng * 16, (ks + 1) * 2 + b_ch), bh[nxt][ng]);
                #pragma unroll
                for (int mt = 0; mt < 4; mt++)
                    ldsm4(sA + swz(arow_s + mt * 16, (ks + 1) * 2 + a_ch), ah[nxt][mt]);
            }
            #pragma unroll
            for (int mt = 0; mt < 4; mt++)
                #pragma unroll
                for (int nt = 0; nt < 8; nt++)
                    mma16816(acc[mt][nt], ah[cur][mt], bh[cur][nt >> 1] + (nt & 1) * 2);
        }
        sl++; if (sl == NST) sl = 0;
    }

    // ---- epilogue: (gated) bias + tanh + hist/logits/Z + |Z| partial ----
    float asum = 0.0f;
    const int lrow = lane >> 2;
    const int lcol = (lane & 3) * 2;
    #pragma unroll
    for (int mt = 0; mt < 4; mt++) {
        #pragma unroll
        for (int half = 0; half < 2; half++) {
            const int m = m0 + wm * 64 + mt * 16 + lrow + half * 8;
            #pragma unroll
            for (int nt = 0; nt < 8; nt++) {
                const int n = n0 + wn * 64 + nt * 8 + lcol;
                float b0 = 0.0f, b1 = 0.0f;
                if (bb4) {
                    int o = n >> 11, nn = n & 2047;
                    #pragma unroll
                    for (int ia = 0; ia < A_NUM; ia++) {
                        const float* row = bb4 + (size_t)(o * A_NUM + ia) * AREA_N + nn;
                        b0 += s_gate[ia] * __ldg(row);
                        b1 += s_gate[ia] * __ldg(row + 1);
                    }
                } else if (bias) {
                    b0 = __ldg(bias + n);
                    b1 = __ldg(bias + n + 1);
                }
                float v0 = acc[mt][nt][half * 2 + 0] + b0;
                float v1 = acc[mt][nt][half * 2 + 1] + b1;
                if (do_tanh) { v0 = tanhf(v0); v1 = tanhf(v1); }
                asum += fabsf(v0) + fabsf(v1);
                if (hist) {
                    int a = n >> 11, nn = n & 2047;
                    *(float2*)(hist + ((size_t)a * BATCH + m) * AREA_N + nn) =
                        make_float2(v0, v1);
                }
                if (logits)
                    *(float2*)(logits + (size_t)m * logitsN + n) = make_float2(v0, v1);
                if (Zfo)
                    *(uint32_t*)(Zfo + (size_t)m * NTOT + n) =
                        pack2h(__float2half_rn(v0), __float2half_rn(v1));
            }
        }
    }

    if (tsum_out) {
        #pragma unroll
        for (int o = 16; o; o >>= 1) asum += __shfl_xor_sync(0xffffffffu, asum, o);
        if (lane == 0) s_wsum[wid] = asum;
        __syncthreads();
        if (tid == 0)
            tsum_out[blockIdx.y * 64 + blockIdx.x] =
                (s_wsum[0] + s_wsum[1]) + (s_wsum[2] + s_wsum[3]);
    }
}

// ------------------------- launch -------------------------
extern "C" void kernel_launch(void* const* d_in, const int* in_sizes, int n_in,
                              void* d_out, int out_size) {
    const float* x    = (const float*)d_in[0];
    const float* Rw   = (const float*)d_in[1];
    const float* rb   = (const float*)d_in[2];
    const float* Wb   = (const float*)d_in[3];
    const float* bb   = (const float*)d_in[4];
    const float* mask = (const float*)d_in[5];
    const float* Ow   = (const float*)d_in[6];
    const float* Ob   = (const float*)d_in[7];
    const int*   aidx = (const int*)d_in[8];

    float* out  = (float*)d_out;
    float* hist = out + LOGITS_ELEMS;

    __half *whi, *rhi, *ohi, *xf, *zf[2];
    float *ts[2], *part;
    cudaGetSymbolAddress((void**)&whi, g_Whi);
    cudaGetSymbolAddress((void**)&rhi, g_Rhi);
    cudaGetSymbolAddress((void**)&ohi, g_Ohi);
    cudaGetSymbolAddress((void**)&xf,  g_xf);
    cudaGetSymbolAddress((void**)&zf[0], g_Zf0);
    cudaGetSymbolAddress((void**)&zf[1], g_Zf1);
    cudaGetSymbolAddress((void**)&ts[0], g_tsA);
    cudaGetSymbolAddress((void**)&ts[1], g_tsB);
    cudaGetSymbolAddress((void**)&part,  g_part);

    cudaFuncSetAttribute(god_gemm, cudaFuncAttributeMaxDynamicSharedMemorySize, SMEM_DYN);

    // prep (single stream; fork experiment reverted — R13 post-mortem)
    prep_xf<<<1024, 256>>>(x);
    prep_rhalf<<<1024, 256>>>((const float4*)Rw);
    prep_ohalf<<<8192, 256>>>(Ow, aidx);

    // encode (K=1024): Z0 = tanh(x @ Rw^T + rb); writes hist[0], Z0, tsum[0]
    god_gemm<<<dim3(64, 4), 128, SMEM_DYN>>>(
        xf, rhi, D_INPUT, D_INPUT / BK,
        0, nullptr, rb, nullptr,
        hist, nullptr, 0, 0,
        zf[0], ts[0], 1);

    // W prep (needed before tick 1) — widened streaming kernel
    prep_wsplit<<<2048, 256>>>((const float4*)Wb, (const float4*)mask);

    // ticks (K=8192, area-gated; gates+bias fused; tsum ping-pong)
    int p = 0;
    for (int t = 0; t < NTICKS; t++) {
        god_gemm<<<dim3(64, 4), 128, SMEM_DYN>>>(
            zf[p], whi, NTOT, 0,
            1, ts[t & 1], nullptr, bb,
            hist + (size_t)(t + 1) * HIST_STEP, nullptr, 0, 0,
            zf[1 - p], ts[(t & 1) ^ 1], 1);
        p ^= 1;
    }

    // logits: one 3D launch, 16-way split-K, then reduce (+Ob)
    god_gemm<<<dim3(8, 4, LOG_SPLIT), 128, SMEM_DYN>>>(
        zf[p], ohi, NTOT, LOG_KTILES,
        0, nullptr, nullptr, nullptr,
        nullptr, part, NCLS, (size_t)LOGITS_ELEMS,
        nullptr, nullptr, 0);
    logits_reduce<<<LOGITS_ELEMS / 1024, 256>>>(Ob, out);
}

// round 16
// speedup vs baseline: 1.5137x; 1.0253x over previous
#include <cuda_runtime.h>
#include <cuda_fp16.h>
#include <math.h>
#include <stdint.h>

// ---------------------------------------------------------------------------
// GodAreaModel via mma.sync fp16, single-term (C = A*Bh).
// R15: logits GEMM skips exactly-zero areas (bit-identical; big win when
// tick-4 gates are all off => Z4 == 0); parallel gate prologue.
// ---------------------------------------------------------------------------

#define A_NUM   4
#define AREA_N  2048
#define NTOT    8192
#define D_INPUT 1024
#define NCLS    1024
#define BATCH   512
#define NTICKS  4
#define THRESH  0.05f
#define LOGITS_ELEMS (BATCH * NCLS)
#define HIST_STEP    (A_NUM * BATCH * AREA_N)

// Block tile
#define BM 128
#define BN 128
#define BK 64
#define A_TILE_BYTES (BM * BK * 2)          // 16384
#define B_TILE_BYTES (BN * BK * 2)          // 16384
#define ST_BYTES (A_TILE_BYTES + B_TILE_BYTES)  // 32768
#define NST 3
#define SMEM_DYN (NST * ST_BYTES)           // 98304 -> 2 CTAs/SM

#define LOG_SPLIT 16
#define LOG_KTILES (NTOT / BK / LOG_SPLIT)  // 8

// gate modes
#define GM_NONE 0
#define GM_THRESH 1   // skip areas with mean|Z| <= THRESH (matches reference gating)
#define GM_ZERO 2     // skip areas whose |Z| sum is exactly 0 (bit-identical shortcut)

// ------------------------- device scratch -------------------------
__device__ __align__(256) __half g_Whi[(size_t)NTOT * NTOT];
__device__ __align__(256) __half g_Rhi[(size_t)NTOT * D_INPUT];
__device__ __align__(256) __half g_Ohi[(size_t)NCLS * NTOT];
__device__ __align__(256) __half g_xf [(size_t)BATCH * D_INPUT];
__device__ __align__(256) __half g_Zf0[(size_t)BATCH * NTOT];
__device__ __align__(256) __half g_Zf1[(size_t)BATCH * NTOT];
__device__ __align__(256) float g_part[(size_t)LOG_SPLIT * LOGITS_ELEMS];
__device__ __align__(256) float g_tsA[256];
__device__ __align__(256) float g_tsB[256];

// ------------------------- helpers -------------------------
__device__ __forceinline__ uint32_t smem_u32(const void* p) {
    return (uint32_t)__cvta_generic_to_shared(p);
}
__device__ __forceinline__ uint32_t pack2h(__half a, __half b) {
    __half2 v; v.x = a; v.y = b;
    return *reinterpret_cast<uint32_t*>(&v);
}
__device__ __forceinline__ void cp16(uint32_t saddr, const void* g) {
    asm volatile("cp.async.cg.shared.global [%0], [%1], 16;" :: "r"(saddr), "l"(g));
}
template<int N>
__device__ __forceinline__ void cp_wait() {
    asm volatile("cp.async.wait_group %0;" :: "n"(N) : "memory");
}
__device__ __forceinline__ uint32_t swz(uint32_t row, uint32_t chunk) {
    return row * 128u + ((chunk ^ (row & 7u)) << 4);
}
__device__ __forceinline__ void ldsm4(uint32_t addr, uint32_t* r) {
    asm volatile("ldmatrix.sync.aligned.m8n8.x4.shared.b16 {%0,%1,%2,%3}, [%4];"
                 : "=r"(r[0]), "=r"(r[1]), "=r"(r[2]), "=r"(r[3]) : "r"(addr));
}
__device__ __forceinline__ void mma16816(float* c, const uint32_t* a, const uint32_t* b) {
    asm volatile(
        "mma.sync.aligned.m16n8k16.row.col.f32.f16.f16.f32 "
        "{%0,%1,%2,%3}, {%4,%5,%6,%7}, {%8,%9}, {%0,%1,%2,%3};"
        : "+f"(c[0]), "+f"(c[1]), "+f"(c[2]), "+f"(c[3])
        : "r"(a[0]), "r"(a[1]), "r"(a[2]), "r"(a[3]), "r"(b[0]), "r"(b[1]));
}
__device__ __forceinline__ uint2 clamp_pack8_lo(float4 w, float4 mk) {
    float v0 = w.x * fminf(fmaxf(mk.x, 0.f), 1.f);
    float v1 = w.y * fminf(fmaxf(mk.y, 0.f), 1.f);
    float v2 = w.z * fminf(fmaxf(mk.z, 0.f), 1.f);
    float v3 = w.w * fminf(fmaxf(mk.w, 0.f), 1.f);
    uint2 r;
    r.x = pack2h(__float2half_rn(v0), __float2half_rn(v1));
    r.y = pack2h(__float2half_rn(v2), __float2half_rn(v3));
    return r;
}

// ------------------------- prep kernels -------------------------
__global__ void prep_wsplit(const float4* __restrict__ W, const float4* __restrict__ mask) {
    const size_t total = (size_t)NTOT * NTOT / 8;
    const size_t stride = (size_t)gridDim.x * blockDim.x;
    for (size_t q = (size_t)blockIdx.x * blockDim.x + threadIdx.x; q < total; q += stride) {
        float4 w0  = W[q * 2];
        float4 w1  = W[q * 2 + 1];
        float4 mk0 = mask[q * 2];
        float4 mk1 = mask[q * 2 + 1];
        size_t s = q * 8;
        int m = (int)(s & 2047);
        size_t r = s >> 11;
        int n = (int)(r & 2047); r >>= 11;
        int i = (int)(r & 3);
        int o = (int)(r >> 2);
        size_t dst = ((size_t)((o << 11) | n)) * NTOT + ((i << 11) | m);
        uint2 lo = clamp_pack8_lo(w0, mk0);
        uint2 hi = clamp_pack8_lo(w1, mk1);
        uint4 out4;
        out4.x = lo.x; out4.y = lo.y; out4.z = hi.x; out4.w = hi.y;
        *(uint4*)(g_Whi + dst) = out4;
    }
}
__global__ void prep_rhalf(const float4* __restrict__ Rw) {
    const size_t total = (size_t)NTOT * D_INPUT / 8;
    const size_t stride = (size_t)gridDim.x * blockDim.x;
    for (size_t q = (size_t)blockIdx.x * blockDim.x + threadIdx.x; q < total; q += stride) {
        float4 w0 = Rw[q * 2];
        float4 w1 = Rw[q * 2 + 1];
        uint4 out4;
        out4.x = pack2h(__float2half_rn(w0.x), __float2half_rn(w0.y));
        out4.y = pack2h(__float2half_rn(w0.z), __float2half_rn(w0.w));
        out4.z = pack2h(__float2half_rn(w1.x), __float2half_rn(w1.y));
        out4.w = pack2h(__float2half_rn(w1.z), __float2half_rn(w1.w));
        *(uint4*)(g_Rhi + q * 8) = out4;
    }
}
__global__ void prep_ohalf(const float* __restrict__ Ow, const int* __restrict__ aidx) {
    size_t s = ((size_t)blockIdx.x * blockDim.x + threadIdx.x) * 4;
    int k = (int)(s & 8191);
    int c = (int)(s >> 13);
    const float* row = Ow + (size_t)c * NTOT;
    const int* ai = aidx + k;
    float w0 = row[ai[0]];
    float w1 = row[ai[1]];
    float w2 = row[ai[2]];
    float w3 = row[ai[3]];
    uint2 out;
    out.x = pack2h(__float2half_rn(w0), __float2half_rn(w1));
    out.y = pack2h(__float2half_rn(w2), __float2half_rn(w3));
    *(uint2*)(g_Ohi + s) = out;
}
__global__ void prep_xf(const float* __restrict__ x) {
    size_t s = ((size_t)blockIdx.x * blockDim.x + threadIdx.x) * 2;
    float2 w = *(const float2*)(x + s);
    *(uint32_t*)(g_xf + s) = pack2h(__float2half_rn(w.x), __float2half_rn(w.y));
}
__global__ void logits_reduce(const float* __restrict__ Ob, float* __restrict__ out) {
    int i = (blockIdx.x * 256 + threadIdx.x) * 4;
    float4 a = *(const float4*)(g_part + i);
    #pragma unroll
    for (int s = 1; s < LOG_SPLIT; s++) {
        float4 b = *(const float4*)(g_part + (size_t)s * LOGITS_ELEMS + i);
        a.x += b.x; a.y += b.y; a.z += b.z; a.w += b.w;
    }
    int n = i & (NCLS - 1);
    float4 ob = *(const float4*)(Ob + n);
    a.x += ob.x; a.y += ob.y; a.z += ob.z; a.w += ob.w;
    *(float4*)(out + i) = a;
}

// ------------------------- stage loader (128 threads) -------------------------
__device__ __forceinline__ void load_tile128(uint32_t sb, const __half* g, int ld, int tid) {
    #pragma unroll
    for (int r = 0; r < 8; r++) {
        int id = tid + r * 128;
        uint32_t row = (uint32_t)id >> 3, c = (uint32_t)id & 7;
        cp16(sb + swz(row, c), g + (size_t)row * ld + c * 8);
    }
}
__device__ __forceinline__ void load_stage(
    uint32_t sb, const __half* Af, const __half* Bh,
    int m0, int n0, int k0, int ld, int tid)
{
    load_tile128(sb,                Af + (size_t)m0 * ld + k0, ld, tid);
    load_tile128(sb + A_TILE_BYTES, Bh + (size_t)n0 * ld + k0, ld, tid);
    asm volatile("cp.async.commit_group;" ::: "memory");
}

// ------------------------- main GEMM -------------------------
// grid (N/BN, M/BM, zsplit). 4 warps: 2(m) x 2(n), warp tile 64x64.
__global__ __launch_bounds__(128, 2)
void god_gemm(const __half* __restrict__ Af, const __half* __restrict__ Bh,
              int ldk, int ktiles_in,
              int gate_mode,
              const float* __restrict__ tsum_in,
              const float* __restrict__ bias,
              const float* __restrict__ bb4,
              float* __restrict__ hist,
              float* __restrict__ logits, int logitsN, size_t zstride,
              __half* __restrict__ Zfo,
              float* __restrict__ tsum_out,
              int do_tanh)
{
    extern __shared__ char dsm[];
    __shared__ float s_gate[A_NUM];
    __shared__ float s_part[128];
    __shared__ float s_wsum[4];

    const int tid  = threadIdx.x;
    const int wid  = tid >> 5, lane = tid & 31;
    const int wm   = wid >> 1;
    const int wn   = wid & 1;
    const int m0   = blockIdx.y * BM;
    const int n0   = blockIdx.x * BN;
    const int k0tile = blockIdx.z * ktiles_in;
    const uint32_t sbase = smem_u32(dsm);
    if (logits) logits += (size_t)blockIdx.z * zstride;

    // gates from producer's 256 tilesums (deterministic, fixed order,
    // parallel 128-thread staging instead of 4x64 serial loads)
    if (gate_mode != GM_NONE) {
        s_part[tid] = __ldg(tsum_in + tid) + __ldg(tsum_in + tid + 128);
        __syncthreads();
        if (tid < A_NUM) {
            float s = 0.0f;
            // area a covers x in [a*16, a*16+16), entries at (y*64 + x), y in {0,1}
            #pragma unroll
            for (int y = 0; y < 2; y++)
                for (int xx = 0; xx < 16; xx++)
                    s += s_part[y * 64 + tid * 16 + xx];
            float g;
            if (gate_mode == GM_THRESH)
                g = (s * (1.0f / (float)(BATCH * AREA_N)) > THRESH) ? 1.0f : 0.0f;
            else  // GM_ZERO: skip only exactly-zero areas (bit-identical)
                g = (s != 0.0f) ? 1.0f : 0.0f;
            s_gate[tid] = g;
        }
    } else if (tid < A_NUM) {
        s_gate[tid] = 1.0f;
    }
    __syncthreads();

    int aa[A_NUM];
    int nact;
    int use_map;
    if (gate_mode == GM_THRESH) {
        int c = 0;
        #pragma unroll
        for (int a = 0; a < A_NUM; a++)
            if (s_gate[a] != 0.0f) aa[c++] = a;
        nact = c * 32;
        use_map = 1;
    } else if (gate_mode == GM_ZERO) {
        // split-K chunk lies entirely inside one area (LOG_KTILES=8, area=32 ktiles)
        int area = k0tile >> 5;
        nact = (s_gate[area] != 0.0f) ? ktiles_in : 0;
        use_map = 0;
        aa[0] = 0;
    } else {
        nact = ktiles_in;
        use_map = 0;
        aa[0] = 0;
    }
    #define KT(i) (use_map ? (aa[(i) >> 5] * 32 + ((i) & 31)) : (k0tile + (i)))

    float acc[4][8][4];
    #pragma unroll
    for (int a = 0; a < 4; a++)
        #pragma unroll
        for (int b = 0; b < 8; b++)
            #pragma unroll
            for (int c = 0; c < 4; c++) acc[a][b][c] = 0.0f;

    const uint32_t a_row = (lane & 7) + ((lane >> 3) & 1) * 8;
    const uint32_t a_ch  = (lane >> 4);
    const uint32_t b_row = (lane & 7) + (lane >> 4) * 8;
    const uint32_t b_ch  = (lane >> 3) & 1;
    const uint32_t arow_s = wm * 64 + a_row;
    const uint32_t brow_s = wn * 64 + b_row;

    #pragma unroll
    for (int s = 0; s < NST - 1; s++)
        if (s < nact)
            load_stage(sbase + (uint32_t)s * ST_BYTES, Af, Bh,
                       m0, n0, KT(s) * BK, ldk, tid);

    uint32_t ah[2][4][4], bh[2][4][4];

    int sl = 0;
    #pragma unroll 1
    for (int i = 0; i < nact; i++) {
        if (nact - i - 1 >= NST - 2) cp_wait<NST - 2>();
        else                         cp_wait<0>();
        __syncthreads();

        if (i + NST - 1 < nact) {
            int s2 = sl + NST - 1; if (s2 >= NST) s2 -= NST;
            load_stage(sbase + (uint32_t)s2 * ST_BYTES, Af, Bh,
                       m0, n0, KT(i + NST - 1) * BK, ldk, tid);
        }

        const uint32_t sA = sbase + (uint32_t)sl * ST_BYTES;
        const uint32_t sB = sA + A_TILE_BYTES;

        #pragma unroll
        for (int ng = 0; ng < 4; ng++)
            ldsm4(sB + swz(brow_s + ng * 16, b_ch), bh[0][ng]);
        #pragma unroll
        for (int mt = 0; mt < 4; mt++)
            ldsm4(sA + swz(arow_s + mt * 16, a_ch), ah[0][mt]);

        #pragma unroll
        for (int ks = 0; ks < 4; ks++) {
            const int cur = ks & 1, nxt = cur ^ 1;
            if (ks < 3) {
                #pragma unroll
                for (int ng = 0; ng < 4; ng++)
                    ldsm4(sB + swz(brow_s + ng * 16, (ks + 1) * 2 + b_ch), bh[nxt][ng]);
                #pragma unroll
                for (int mt = 0; mt < 4; mt++)
                    ldsm4(sA + swz(arow_s + mt * 16, (ks + 1) * 2 + a_ch), ah[nxt][mt]);
            }
            #pragma unroll
            for (int mt = 0; mt < 4; mt++)
                #pragma unroll
                for (int nt = 0; nt < 8; nt++)
                    mma16816(acc[mt][nt], ah[cur][mt], bh[cur][nt >> 1] + (nt & 1) * 2);
        }
        sl++; if (sl == NST) sl = 0;
    }

    // ---- epilogue: (gated) bias + tanh + hist/logits/Z + |Z| partial ----
    float asum = 0.0f;
    const int lrow = lane >> 2;
    const int lcol = (lane & 3) * 2;
    #pragma unroll
    for (int mt = 0; mt < 4; mt++) {
        #pragma unroll
        for (int half = 0; half < 2; half++) {
            const int m = m0 + wm * 64 + mt * 16 + lrow + half * 8;
            #pragma unroll
            for (int nt = 0; nt < 8; nt++) {
                const int n = n0 + wn * 64 + nt * 8 + lcol;
                float b0 = 0.0f, b1 = 0.0f;
                if (bb4) {
                    int o = n >> 11, nn = n & 2047;
                    #pragma unroll
                    for (int ia = 0; ia < A_NUM; ia++) {
                        const float* row = bb4 + (size_t)(o * A_NUM + ia) * AREA_N + nn;
                        b0 += s_gate[ia] * __ldg(row);
                        b1 += s_gate[ia] * __ldg(row + 1);
                    }
                } else if (bias) {
                    b0 = __ldg(bias + n);
                    b1 = __ldg(bias + n + 1);
                }
                float v0 = acc[mt][nt][half * 2 + 0] + b0;
                float v1 = acc[mt][nt][half * 2 + 1] + b1;
                if (do_tanh) { v0 = tanhf(v0); v1 = tanhf(v1); }
                asum += fabsf(v0) + fabsf(v1);
                if (hist) {
                    int a = n >> 11, nn = n & 2047;
                    *(float2*)(hist + ((size_t)a * BATCH + m) * AREA_N + nn) =
                        make_float2(v0, v1);
                }
                if (logits)
                    *(float2*)(logits + (size_t)m * logitsN + n) = make_float2(v0, v1);
                if (Zfo)
                    *(uint32_t*)(Zfo + (size_t)m * NTOT + n) =
                        pack2h(__float2half_rn(v0), __float2half_rn(v1));
            }
        }
    }

    if (tsum_out) {
        #pragma unroll
        for (int o = 16; o; o >>= 1) asum += __shfl_xor_sync(0xffffffffu, asum, o);
        if (lane == 0) s_wsum[wid] = asum;
        __syncthreads();
        if (tid == 0)
            tsum_out[blockIdx.y * 64 + blockIdx.x] =
                (s_wsum[0] + s_wsum[1]) + (s_wsum[2] + s_wsum[3]);
    }
}

// ------------------------- launch -------------------------
extern "C" void kernel_launch(void* const* d_in, const int* in_sizes, int n_in,
                              void* d_out, int out_size) {
    const float* x    = (const float*)d_in[0];
    const float* Rw   = (const float*)d_in[1];
    const float* rb   = (const float*)d_in[2];
    const float* Wb   = (const float*)d_in[3];
    const float* bb   = (const float*)d_in[4];
    const float* mask = (const float*)d_in[5];
    const float* Ow   = (const float*)d_in[6];
    const float* Ob   = (const float*)d_in[7];
    const int*   aidx = (const int*)d_in[8];

    float* out  = (float*)d_out;
    float* hist = out + LOGITS_ELEMS;

    __half *whi, *rhi, *ohi, *xf, *zf[2];
    float *ts[2], *part;
    cudaGetSymbolAddress((void**)&whi, g_Whi);
    cudaGetSymbolAddress((void**)&rhi, g_Rhi);
    cudaGetSymbolAddress((void**)&ohi, g_Ohi);
    cudaGetSymbolAddress((void**)&xf,  g_xf);
    cudaGetSymbolAddress((void**)&zf[0], g_Zf0);
    cudaGetSymbolAddress((void**)&zf[1], g_Zf1);
    cudaGetSymbolAddress((void**)&ts[0], g_tsA);
    cudaGetSymbolAddress((void**)&ts[1], g_tsB);
    cudaGetSymbolAddress((void**)&part,  g_part);

    cudaFuncSetAttribute(god_gemm, cudaFuncAttributeMaxDynamicSharedMemorySize, SMEM_DYN);

    // prep (single stream)
    prep_xf<<<1024, 256>>>(x);
    prep_rhalf<<<1024, 256>>>((const float4*)Rw);
    prep_ohalf<<<8192, 256>>>(Ow, aidx);

    // encode (K=1024): Z0 = tanh(x @ Rw^T + rb); writes hist[0], Z0, tsum[0]
    god_gemm<<<dim3(64, 4), 128, SMEM_DYN>>>(
        xf, rhi, D_INPUT, D_INPUT / BK,
        GM_NONE, nullptr, rb, nullptr,
        hist, nullptr, 0, 0,
        zf[0], ts[0], 1);

    // W prep (needed before tick 1)
    prep_wsplit<<<2048, 256>>>((const float4*)Wb, (const float4*)mask);

    // ticks (K=8192, area-gated; gates+bias fused; tsum ping-pong)
    int p = 0;
    for (int t = 0; t < NTICKS; t++) {
        god_gemm<<<dim3(64, 4), 128, SMEM_DYN>>>(
            zf[p], whi, NTOT, 0,
            GM_THRESH, ts[t & 1], nullptr, bb,
            hist + (size_t)(t + 1) * HIST_STEP, nullptr, 0, 0,
            zf[1 - p], ts[(t & 1) ^ 1], 1);
        p ^= 1;
    }
    // after 4 ticks: Z4 tilesums are in ts[0]

    // logits: 16-way split-K; GM_ZERO skips exactly-zero Z4 areas (bit-identical)
    god_gemm<<<dim3(8, 4, LOG_SPLIT), 128, SMEM_DYN>>>(
        zf[p], ohi, NTOT, LOG_KTILES,
        GM_ZERO, ts[0], nullptr, nullptr,
        nullptr, part, NCLS, (size_t)LOGITS_ELEMS,
        nullptr, nullptr, 0);
    logits_reduce<<<LOGITS_ELEMS / 1024, 256>>>(Ob, out);
}

// round 17
// speedup vs baseline: 1.5286x; 1.0099x over previous
#include <cuda_runtime.h>
#include <cuda_fp16.h>
#include <math.h>
#include <stdint.h>

// ---------------------------------------------------------------------------
// GodAreaModel via mma.sync fp16, single-term (C = A*Bh).
// R16: all prep fused into ONE kernel (block-range dispatch) -> 8 launches,
// grid-level overlap of independent prep phases. GEMM unchanged (R15).
// ---------------------------------------------------------------------------

#define A_NUM   4
#define AREA_N  2048
#define NTOT    8192
#define D_INPUT 1024
#define NCLS    1024
#define BATCH   512
#define NTICKS  4
#define THRESH  0.05f
#define LOGITS_ELEMS (BATCH * NCLS)
#define HIST_STEP    (A_NUM * BATCH * AREA_N)

// Block tile
#define BM 128
#define BN 128
#define BK 64
#define A_TILE_BYTES (BM * BK * 2)
#define B_TILE_BYTES (BN * BK * 2)
#define ST_BYTES (A_TILE_BYTES + B_TILE_BYTES)  // 32768
#define NST 3
#define SMEM_DYN (NST * ST_BYTES)               // 98304 -> 2 CTAs/SM

#define LOG_SPLIT 16
#define LOG_KTILES (NTOT / BK / LOG_SPLIT)      // 8

// gate modes
#define GM_NONE 0
#define GM_THRESH 1
#define GM_ZERO 2

// prep_all block ranges
#define PB_XF     1024
#define PB_RHALF  1024
#define PB_OHALF  8192
#define PB_WSPLIT 2048
#define PB_TOTAL  (PB_XF + PB_RHALF + PB_OHALF + PB_WSPLIT)

// ------------------------- device scratch -------------------------
__device__ __align__(256) __half g_Whi[(size_t)NTOT * NTOT];
__device__ __align__(256) __half g_Rhi[(size_t)NTOT * D_INPUT];
__device__ __align__(256) __half g_Ohi[(size_t)NCLS * NTOT];
__device__ __align__(256) __half g_xf [(size_t)BATCH * D_INPUT];
__device__ __align__(256) __half g_Zf0[(size_t)BATCH * NTOT];
__device__ __align__(256) __half g_Zf1[(size_t)BATCH * NTOT];
__device__ __align__(256) float g_part[(size_t)LOG_SPLIT * LOGITS_ELEMS];
__device__ __align__(256) float g_tsA[256];
__device__ __align__(256) float g_tsB[256];

// ------------------------- helpers -------------------------
__device__ __forceinline__ uint32_t smem_u32(const void* p) {
    return (uint32_t)__cvta_generic_to_shared(p);
}
__device__ __forceinline__ uint32_t pack2h(__half a, __half b) {
    __half2 v; v.x = a; v.y = b;
    return *reinterpret_cast<uint32_t*>(&v);
}
__device__ __forceinline__ void cp16(uint32_t saddr, const void* g) {
    asm volatile("cp.async.cg.shared.global [%0], [%1], 16;" :: "r"(saddr), "l"(g));
}
template<int N>
__device__ __forceinline__ void cp_wait() {
    asm volatile("cp.async.wait_group %0;" :: "n"(N) : "memory");
}
__device__ __forceinline__ uint32_t swz(uint32_t row, uint32_t chunk) {
    return row * 128u + ((chunk ^ (row & 7u)) << 4);
}
__device__ __forceinline__ void ldsm4(uint32_t addr, uint32_t* r) {
    asm volatile("ldmatrix.sync.aligned.m8n8.x4.shared.b16 {%0,%1,%2,%3}, [%4];"
                 : "=r"(r[0]), "=r"(r[1]), "=r"(r[2]), "=r"(r[3]) : "r"(addr));
}
__device__ __forceinline__ void mma16816(float* c, const uint32_t* a, const uint32_t* b) {
    asm volatile(
        "mma.sync.aligned.m16n8k16.row.col.f32.f16.f16.f32 "
        "{%0,%1,%2,%3}, {%4,%5,%6,%7}, {%8,%9}, {%0,%1,%2,%3};"
        : "+f"(c[0]), "+f"(c[1]), "+f"(c[2]), "+f"(c[3])
        : "r"(a[0]), "r"(a[1]), "r"(a[2]), "r"(a[3]), "r"(b[0]), "r"(b[1]));
}
__device__ __forceinline__ uint2 clamp_pack8_lo(float4 w, float4 mk) {
    float v0 = w.x * fminf(fmaxf(mk.x, 0.f), 1.f);
    float v1 = w.y * fminf(fmaxf(mk.y, 0.f), 1.f);
    float v2 = w.z * fminf(fmaxf(mk.z, 0.f), 1.f);
    float v3 = w.w * fminf(fmaxf(mk.w, 0.f), 1.f);
    uint2 r;
    r.x = pack2h(__float2half_rn(v0), __float2half_rn(v1));
    r.y = pack2h(__float2half_rn(v2), __float2half_rn(v3));
    return r;
}

// ------------------------- fused prep kernel -------------------------
// Block-range dispatch: [xf | rhalf | ohalf | wsplit]. All phases independent;
// short phases finish early and the freed SMs accelerate wsplit's tail.
__global__ void prep_all(const float* __restrict__ x,
                         const float4* __restrict__ Rw,
                         const float* __restrict__ Ow,
                         const int* __restrict__ aidx,
                         const float4* __restrict__ W,
                         const float4* __restrict__ mask) {
    const int b = blockIdx.x;
    const int tid = threadIdx.x;
    if (b < PB_XF) {
        size_t s = ((size_t)b * 256 + tid) * 2;
        float2 w = *(const float2*)(x + s);
        *(uint32_t*)(g_xf + s) = pack2h(__float2half_rn(w.x), __float2half_rn(w.y));
    } else if (b < PB_XF + PB_RHALF) {
        const size_t nthr = (size_t)PB_RHALF * 256;
        const size_t total = (size_t)NTOT * D_INPUT / 8;
        for (size_t q = (size_t)(b - PB_XF) * 256 + tid; q < total; q += nthr) {
            float4 w0 = Rw[q * 2];
            float4 w1 = Rw[q * 2 + 1];
            uint4 out4;
            out4.x = pack2h(__float2half_rn(w0.x), __float2half_rn(w0.y));
            out4.y = pack2h(__float2half_rn(w0.z), __float2half_rn(w0.w));
            out4.z = pack2h(__float2half_rn(w1.x), __float2half_rn(w1.y));
            out4.w = pack2h(__float2half_rn(w1.z), __float2half_rn(w1.w));
            *(uint4*)(g_Rhi + q * 8) = out4;
        }
    } else if (b < PB_XF + PB_RHALF + PB_OHALF) {
        size_t s = ((size_t)(b - PB_XF - PB_RHALF) * 256 + tid) * 4;
        int k = (int)(s & 8191);
        int c = (int)(s >> 13);
        const float* row = Ow + (size_t)c * NTOT;
        const int* ai = aidx + k;
        float w0 = row[ai[0]];
        float w1 = row[ai[1]];
        float w2 = row[ai[2]];
        float w3 = row[ai[3]];
        uint2 out;
        out.x = pack2h(__float2half_rn(w0), __float2half_rn(w1));
        out.y = pack2h(__float2half_rn(w2), __float2half_rn(w3));
        *(uint2*)(g_Ohi + s) = out;
    } else {
        const size_t nthr = (size_t)PB_WSPLIT * 256;
        const size_t total = (size_t)NTOT * NTOT / 8;
        for (size_t q = (size_t)(b - PB_XF - PB_RHALF - PB_OHALF) * 256 + tid;
             q < total; q += nthr) {
            float4 w0  = W[q * 2];
            float4 w1  = W[q * 2 + 1];
            float4 mk0 = mask[q * 2];
            float4 mk1 = mask[q * 2 + 1];
            size_t s = q * 8;
            int m = (int)(s & 2047);
            size_t r = s >> 11;
            int n = (int)(r & 2047); r >>= 11;
            int i = (int)(r & 3);
            int o = (int)(r >> 2);
            size_t dst = ((size_t)((o << 11) | n)) * NTOT + ((i << 11) | m);
            uint2 lo = clamp_pack8_lo(w0, mk0);
            uint2 hi = clamp_pack8_lo(w1, mk1);
            uint4 out4;
            out4.x = lo.x; out4.y = lo.y; out4.z = hi.x; out4.w = hi.y;
            *(uint4*)(g_Whi + dst) = out4;
        }
    }
}

__global__ void logits_reduce(const float* __restrict__ Ob, float* __restrict__ out) {
    int i = (blockIdx.x * 256 + threadIdx.x) * 4;
    float4 a = *(const float4*)(g_part + i);
    #pragma unroll
    for (int s = 1; s < LOG_SPLIT; s++) {
        float4 b = *(const float4*)(g_part + (size_t)s * LOGITS_ELEMS + i);
        a.x += b.x; a.y += b.y; a.z += b.z; a.w += b.w;
    }
    int n = i & (NCLS - 1);
    float4 ob = *(const float4*)(Ob + n);
    a.x += ob.x; a.y += ob.y; a.z += ob.z; a.w += ob.w;
    *(float4*)(out + i) = a;
}

// ------------------------- stage loader (128 threads) -------------------------
__device__ __forceinline__ void load_tile128(uint32_t sb, const __half* g, int ld, int tid) {
    #pragma unroll
    for (int r = 0; r < 8; r++) {
        int id = tid + r * 128;
        uint32_t row = (uint32_t)id >> 3, c = (uint32_t)id & 7;
        cp16(sb + swz(row, c), g + (size_t)row * ld + c * 8);
    }
}
__device__ __forceinline__ void load_stage(
    uint32_t sb, const __half* Af, const __half* Bh,
    int m0, int n0, int k0, int ld, int tid)
{
    load_tile128(sb,                Af + (size_t)m0 * ld + k0, ld, tid);
    load_tile128(sb + A_TILE_BYTES, Bh + (size_t)n0 * ld + k0, ld, tid);
    asm volatile("cp.async.commit_group;" ::: "memory");
}

// ------------------------- main GEMM -------------------------
// grid (N/BN, M/BM, zsplit). 4 warps: 2(m) x 2(n), warp tile 64x64.
__global__ __launch_bounds__(128, 2)
void god_gemm(const __half* __restrict__ Af, const __half* __restrict__ Bh,
              int ldk, int ktiles_in,
              int gate_mode,
              const float* __restrict__ tsum_in,
              const float* __restrict__ bias,
              const float* __restrict__ bb4,
              float* __restrict__ hist,
              float* __restrict__ logits, int logitsN, size_t zstride,
              __half* __restrict__ Zfo,
              float* __restrict__ tsum_out,
              int do_tanh)
{
    extern __shared__ char dsm[];
    __shared__ float s_gate[A_NUM];
    __shared__ float s_part[128];
    __shared__ float s_wsum[4];

    const int tid  = threadIdx.x;
    const int wid  = tid >> 5, lane = tid & 31;
    const int wm   = wid >> 1;
    const int wn   = wid & 1;
    const int m0   = blockIdx.y * BM;
    const int n0   = blockIdx.x * BN;
    const int k0tile = blockIdx.z * ktiles_in;
    const uint32_t sbase = smem_u32(dsm);
    if (logits) logits += (size_t)blockIdx.z * zstride;

    if (gate_mode != GM_NONE) {
        s_part[tid] = __ldg(tsum_in + tid) + __ldg(tsum_in + tid + 128);
        __syncthreads();
        if (tid < A_NUM) {
            float s = 0.0f;
            #pragma unroll
            for (int y = 0; y < 2; y++)
                for (int xx = 0; xx < 16; xx++)
                    s += s_part[y * 64 + tid * 16 + xx];
            float g;
            if (gate_mode == GM_THRESH)
                g = (s * (1.0f / (float)(BATCH * AREA_N)) > THRESH) ? 1.0f : 0.0f;
            else
                g = (s != 0.0f) ? 1.0f : 0.0f;
            s_gate[tid] = g;
        }
    } else if (tid < A_NUM) {
        s_gate[tid] = 1.0f;
    }
    __syncthreads();

    int aa[A_NUM];
    int nact;
    int use_map;
    if (gate_mode == GM_THRESH) {
        int c = 0;
        #pragma unroll
        for (int a = 0; a < A_NUM; a++)
            if (s_gate[a] != 0.0f) aa[c++] = a;
        nact = c * 32;
        use_map = 1;
    } else if (gate_mode == GM_ZERO) {
        int area = k0tile >> 5;
        nact = (s_gate[area] != 0.0f) ? ktiles_in : 0;
        use_map = 0;
        aa[0] = 0;
    } else {
        nact = ktiles_in;
        use_map = 0;
        aa[0] = 0;
    }
    #define KT(i) (use_map ? (aa[(i) >> 5] * 32 + ((i) & 31)) : (k0tile + (i)))

    float acc[4][8][4];
    #pragma unroll
    for (int a = 0; a < 4; a++)
        #pragma unroll
        for (int b = 0; b < 8; b++)
            #pragma unroll
            for (int c = 0; c < 4; c++) acc[a][b][c] = 0.0f;

    const uint32_t a_row = (lane & 7) + ((lane >> 3) & 1) * 8;
    const uint32_t a_ch  = (lane >> 4);
    const uint32_t b_row = (lane & 7) + (lane >> 4) * 8;
    const uint32_t b_ch  = (lane >> 3) & 1;
    const uint32_t arow_s = wm * 64 + a_row;
    const uint32_t brow_s = wn * 64 + b_row;

    #pragma unroll
    for (int s = 0; s < NST - 1; s++)
        if (s < nact)
            load_stage(sbase + (uint32_t)s * ST_BYTES, Af, Bh,
                       m0, n0, KT(s) * BK, ldk, tid);

    uint32_t ah[2][4][4], bh[2][4][4];

    int sl = 0;
    #pragma unroll 1
    for (int i = 0; i < nact; i++) {
        if (nact - i - 1 >= NST - 2) cp_wait<NST - 2>();
        else                         cp_wait<0>();
        __syncthreads();

        if (i + NST - 1 < nact) {
            int s2 = sl + NST - 1; if (s2 >= NST) s2 -= NST;
            load_stage(sbase + (uint32_t)s2 * ST_BYTES, Af, Bh,
                       m0, n0, KT(i + NST - 1) * BK, ldk, tid);
        }

        const uint32_t sA = sbase + (uint32_t)sl * ST_BYTES;
        const uint32_t sB = sA + A_TILE_BYTES;

        #pragma unroll
        for (int ng = 0; ng < 4; ng++)
            ldsm4(sB + swz(brow_s + ng * 16, b_ch), bh[0][ng]);
        #pragma unroll
        for (int mt = 0; mt < 4; mt++)
            ldsm4(sA + swz(arow_s + mt * 16, a_ch), ah[0][mt]);

        #pragma unroll
        for (int ks = 0; ks < 4; ks++) {
            const int cur = ks & 1, nxt = cur ^ 1;
            if (ks < 3) {
                #pragma unroll
                for (int ng = 0; ng < 4; ng++)
                    ldsm4(sB + swz(brow_s + ng * 16, (ks + 1) * 2 + b_ch), bh[nxt][ng]);
                #pragma unroll
                for (int mt = 0; mt < 4; mt++)
                    ldsm4(sA + swz(arow_s + mt * 16, (ks + 1) * 2 + a_ch), ah[nxt][mt]);
            }
            #pragma unroll
            for (int mt = 0; mt < 4; mt++)
                #pragma unroll
                for (int nt = 0; nt < 8; nt++)
                    mma16816(acc[mt][nt], ah[cur][mt], bh[cur][nt >> 1] + (nt & 1) * 2);
        }
        sl++; if (sl == NST) sl = 0;
    }

    // ---- epilogue ----
    float asum = 0.0f;
    const int lrow = lane >> 2;
    const int lcol = (lane & 3) * 2;
    #pragma unroll
    for (int mt = 0; mt < 4; mt++) {
        #pragma unroll
        for (int half = 0; half < 2; half++) {
            const int m = m0 + wm * 64 + mt * 16 + lrow + half * 8;
            #pragma unroll
            for (int nt = 0; nt < 8; nt++) {
                const int n = n0 + wn * 64 + nt * 8 + lcol;
                float b0 = 0.0f, b1 = 0.0f;
                if (bb4) {
                    int o = n >> 11, nn = n & 2047;
                    #pragma unroll
                    for (int ia = 0; ia < A_NUM; ia++) {
                        const float* row = bb4 + (size_t)(o * A_NUM + ia) * AREA_N + nn;
                        b0 += s_gate[ia] * __ldg(row);
                        b1 += s_gate[ia] * __ldg(row + 1);
                    }
                } else if (bias) {
                    b0 = __ldg(bias + n);
                    b1 = __ldg(bias + n + 1);
                }
                float v0 = acc[mt][nt][half * 2 + 0] + b0;
                float v1 = acc[mt][nt][half * 2 + 1] + b1;
                if (do_tanh) { v0 = tanhf(v0); v1 = tanhf(v1); }
                asum += fabsf(v0) + fabsf(v1);
                if (hist) {
                    int a = n >> 11, nn = n & 2047;
                    *(float2*)(hist + ((size_t)a * BATCH + m) * AREA_N + nn) =
                        make_float2(v0, v1);
                }
                if (logits)
                    *(float2*)(logits + (size_t)m * logitsN + n) = make_float2(v0, v1);
                if (Zfo)
                    *(uint32_t*)(Zfo + (size_t)m * NTOT + n) =
                        pack2h(__float2half_rn(v0), __float2half_rn(v1));
            }
        }
    }

    if (tsum_out) {
        #pragma unroll
        for (int o = 16; o; o >>= 1) asum += __shfl_xor_sync(0xffffffffu, asum, o);
        if (lane == 0) s_wsum[wid] = asum;
        __syncthreads();
        if (tid == 0)
            tsum_out[blockIdx.y * 64 + blockIdx.x] =
                (s_wsum[0] + s_wsum[1]) + (s_wsum[2] + s_wsum[3]);
    }
}

// ------------------------- launch -------------------------
extern "C" void kernel_launch(void* const* d_in, const int* in_sizes, int n_in,
                              void* d_out, int out_size) {
    const float* x    = (const float*)d_in[0];
    const float* Rw   = (const float*)d_in[1];
    const float* rb   = (const float*)d_in[2];
    const float* Wb   = (const float*)d_in[3];
    const float* bb   = (const float*)d_in[4];
    const float* mask = (const float*)d_in[5];
    const float* Ow   = (const float*)d_in[6];
    const float* Ob   = (const float*)d_in[7];
    const int*   aidx = (const int*)d_in[8];

    float* out  = (float*)d_out;
    float* hist = out + LOGITS_ELEMS;

    __half *whi, *rhi, *ohi, *xf, *zf[2];
    float *ts[2], *part;
    cudaGetSymbolAddress((void**)&whi, g_Whi);
    cudaGetSymbolAddress((void**)&rhi, g_Rhi);
    cudaGetSymbolAddress((void**)&ohi, g_Ohi);
    cudaGetSymbolAddress((void**)&xf,  g_xf);
    cudaGetSymbolAddress((void**)&zf[0], g_Zf0);
    cudaGetSymbolAddress((void**)&zf[1], g_Zf1);
    cudaGetSymbolAddress((void**)&ts[0], g_tsA);
    cudaGetSymbolAddress((void**)&ts[1], g_tsB);
    cudaGetSymbolAddress((void**)&part,  g_part);

    cudaFuncSetAttribute(god_gemm, cudaFuncAttributeMaxDynamicSharedMemorySize, SMEM_DYN);

    // ONE fused prep kernel: xf | rhalf | ohalf | wsplit (independent phases,
    // grid-level overlap; short phases free SMs for wsplit's tail)
    prep_all<<<PB_TOTAL, 256>>>(x, (const float4*)Rw, Ow, aidx,
                                (const float4*)Wb, (const float4*)mask);

    // encode (K=1024): Z0 = tanh(x @ Rw^T + rb); writes hist[0], Z0, tsum[0]
    god_gemm<<<dim3(64, 4), 128, SMEM_DYN>>>(
        xf, rhi, D_INPUT, D_INPUT / BK,
        GM_NONE, nullptr, rb, nullptr,
        hist, nullptr, 0, 0,
        zf[0], ts[0], 1);

    // ticks (K=8192, area-gated; gates+bias fused; tsum ping-pong)
    int p = 0;
    for (int t = 0; t < NTICKS; t++) {
        god_gemm<<<dim3(64, 4), 128, SMEM_DYN>>>(
            zf[p], whi, NTOT, 0,
            GM_THRESH, ts[t & 1], nullptr, bb,
            hist + (size_t)(t + 1) * HIST_STEP, nullptr, 0, 0,
            zf[1 - p], ts[(t & 1) ^ 1], 1);
        p ^= 1;
    }

    // logits: 16-way split-K; GM_ZERO skips exactly-zero Z4 areas (bit-identical)
    god_gemm<<<dim3(8, 4, LOG_SPLIT), 128, SMEM_DYN>>>(
        zf[p], ohi, NTOT, LOG_KTILES,
        GM_ZERO, ts[0], nullptr, nullptr,
        nullptr, part, NCLS, (size_t)LOGITS_ELEMS,
        nullptr, nullptr, 0);
    logits_reduce<<<LOGITS_ELEMS / 1024, 256>>>(Ob, out);
}